// round 1
// baseline (speedup 1.0000x reference)
#include <cuda_runtime.h>
#include <math.h>

// Problem constants
#define B_  4
#define L_  384
#define H_  128
#define F_  384
#define M1_ (B_ * L_ * L_)   // 589824 edge rows

// Scratch (allocation-free rule: __device__ globals)
__device__ float g_T1[(size_t)M1_ * F_];        // gelu(h_E @ fw1 + fb1)  [905 MB]
__device__ float g_xconv[(size_t)B_ * L_ * F_]; // einsum output          [2.4 MB]
__device__ float g_predm[B_ * L_];              // pred * mask

__device__ __forceinline__ float gelu_f(float x) {
    // exact erf GELU (matches jax approximate=False / torch nn.GELU default)
    return 0.5f * x * (1.0f + erff(x * 0.70710678118654752440f));
}

// ============================================================================
// Kernel A: T1 = gelu(h_E @ fw1 + fb1)
//   M = 589824, K = 128, N = 384. Tile 64(M) x 128(N), K-chunk 32.
//   256 threads, 4x8 microtile per thread.
// ============================================================================
#define TA_M 64
#define TA_N 128
#define TA_K 32

__global__ void __launch_bounds__(256) gemm1_kernel(
    const float* __restrict__ hE,
    const float* __restrict__ fw1,
    const float* __restrict__ fb1)
{
    __shared__ float As[TA_K][TA_M + 4];  // transposed: As[k][m], +4 pad keeps float4 alignment
    __shared__ float Bs[TA_K][TA_N];

    const int m0  = blockIdx.x * TA_M;
    const int n0  = blockIdx.y * TA_N;
    const int tid = threadIdx.x;
    const int tm  = tid >> 4;    // 0..15 -> 4 rows each
    const int tn  = tid & 15;    // 0..15 -> 8 cols each

    float acc[4][8];
#pragma unroll
    for (int i = 0; i < 4; ++i)
#pragma unroll
        for (int j = 0; j < 8; ++j) acc[i][j] = 0.f;

    const int ka = tid & 31, ma = tid >> 5;   // A load mapping (coalesced over k)
    const int nb = tid & 127, kb = tid >> 7;  // B load mapping (coalesced over n)

    for (int kc = 0; kc < H_; kc += TA_K) {
        // A tile: 64 x 32, stored transposed
#pragma unroll
        for (int r = 0; r < 8; ++r)
            As[ka][ma + r * 8] = hE[(size_t)(m0 + ma + r * 8) * H_ + kc + ka];
        // B tile: 32 x 128
#pragma unroll
        for (int r = 0; r < 16; ++r)
            Bs[kb + r * 2][nb] = fw1[(size_t)(kc + kb + r * 2) * F_ + n0 + nb];
        __syncthreads();

#pragma unroll
        for (int kk = 0; kk < TA_K; ++kk) {
            float4 av  = *reinterpret_cast<const float4*>(&As[kk][tm * 4]);
            float4 bv0 = *reinterpret_cast<const float4*>(&Bs[kk][tn * 8]);
            float4 bv1 = *reinterpret_cast<const float4*>(&Bs[kk][tn * 8 + 4]);
            const float a[4] = {av.x, av.y, av.z, av.w};
            const float b[8] = {bv0.x, bv0.y, bv0.z, bv0.w, bv1.x, bv1.y, bv1.z, bv1.w};
#pragma unroll
            for (int i = 0; i < 4; ++i)
#pragma unroll
                for (int j = 0; j < 8; ++j) acc[i][j] += a[i] * b[j];
        }
        __syncthreads();
    }

    // Epilogue: bias + gelu, vectorized stores
    float bias[8];
#pragma unroll
    for (int j = 0; j < 8; ++j) bias[j] = fb1[n0 + tn * 8 + j];

#pragma unroll
    for (int i = 0; i < 4; ++i) {
        const size_t row = (size_t)(m0 + tm * 4 + i) * F_ + n0 + tn * 8;
        float4 o0, o1;
        o0.x = gelu_f(acc[i][0] + bias[0]);
        o0.y = gelu_f(acc[i][1] + bias[1]);
        o0.z = gelu_f(acc[i][2] + bias[2]);
        o0.w = gelu_f(acc[i][3] + bias[3]);
        o1.x = gelu_f(acc[i][4] + bias[4]);
        o1.y = gelu_f(acc[i][5] + bias[5]);
        o1.z = gelu_f(acc[i][6] + bias[6]);
        o1.w = gelu_f(acc[i][7] + bias[7]);
        *reinterpret_cast<float4*>(&g_T1[row])     = o0;
        *reinterpret_cast<float4*>(&g_T1[row + 4]) = o1;
    }
}

// ============================================================================
// Kernel B: per (b,l), per 128-wide f_out tile:
//   T2 = gelu(T1_bl @ fw2 + fb2)        [384 k-edges x 128 f]
//   xconv[b,l,f] = sum_k h_V[b,k,f] * T2[k,f]
// T2 never hits memory. Deterministic in-block tree reduction over k.
// Tile: 128(k-rows, looped 3x) x 128(f), K-chunk 32, 8x8 microtile.
// ============================================================================
#define TB_M 128
#define TB_N 128
#define TB_K 32

__global__ void __launch_bounds__(256) gemm2_kernel(
    const float* __restrict__ fw2,
    const float* __restrict__ fb2,
    const float* __restrict__ hV)
{
    __shared__ float As[TB_K][TB_M + 4];
    __shared__ float Bs[TB_K][TB_N];
    __shared__ float red[16][TB_N];
    __shared__ float xacc[TB_N];

    const int bl  = blockIdx.x;          // b*L + l
    const int b   = bl / L_;
    const int n0  = blockIdx.y * TB_N;   // f_out tile
    const int tid = threadIdx.x;
    const int tm  = tid >> 4;            // 0..15 -> 8 k-rows each
    const int tn  = tid & 15;            // 0..15 -> 8 f-cols each

    const float* A = g_T1 + (size_t)bl * L_ * F_;   // [384 k, 384 f_in]

    if (tid < TB_N) xacc[tid] = 0.f;

    float bias[8];
#pragma unroll
    for (int j = 0; j < 8; ++j) bias[j] = fb2[n0 + tn * 8 + j];

    const int ka = tid & 31, ma = tid >> 5;
    const int nb = tid & 127, kb = tid >> 7;

    for (int mt = 0; mt < 3; ++mt) {
        const int m0 = mt * TB_M;
        float acc[8][8];
#pragma unroll
        for (int i = 0; i < 8; ++i)
#pragma unroll
            for (int j = 0; j < 8; ++j) acc[i][j] = 0.f;

        for (int kc = 0; kc < F_; kc += TB_K) {
#pragma unroll
            for (int r = 0; r < 16; ++r)
                As[ka][ma + r * 8] = A[(size_t)(m0 + ma + r * 8) * F_ + kc + ka];
#pragma unroll
            for (int r = 0; r < 16; ++r)
                Bs[kb + r * 2][nb] = fw2[(size_t)(kc + kb + r * 2) * F_ + n0 + nb];
            __syncthreads();

#pragma unroll
            for (int kk = 0; kk < TB_K; ++kk) {
                float4 av0 = *reinterpret_cast<const float4*>(&As[kk][tm * 8]);
                float4 av1 = *reinterpret_cast<const float4*>(&As[kk][tm * 8 + 4]);
                float4 bv0 = *reinterpret_cast<const float4*>(&Bs[kk][tn * 8]);
                float4 bv1 = *reinterpret_cast<const float4*>(&Bs[kk][tn * 8 + 4]);
                const float a[8] = {av0.x, av0.y, av0.z, av0.w, av1.x, av1.y, av1.z, av1.w};
                const float bb[8] = {bv0.x, bv0.y, bv0.z, bv0.w, bv1.x, bv1.y, bv1.z, bv1.w};
#pragma unroll
                for (int i = 0; i < 8; ++i)
#pragma unroll
                    for (int j = 0; j < 8; ++j) acc[i][j] += a[i] * bb[j];
            }
            __syncthreads();
        }

        // Epilogue: gelu, multiply by h_V[b, k, f], partial-sum over this thread's 8 k-rows
        float part[8];
#pragma unroll
        for (int j = 0; j < 8; ++j) part[j] = 0.f;
#pragma unroll
        for (int i = 0; i < 8; ++i) {
            const int m = m0 + tm * 8 + i;  // k-edge index
            const float* hvrow = hV + ((size_t)b * L_ + m) * F_ + n0 + tn * 8;
#pragma unroll
            for (int j = 0; j < 8; ++j) {
                float v = gelu_f(acc[i][j] + bias[j]);
                part[j] += hvrow[j] * v;
            }
        }
#pragma unroll
        for (int j = 0; j < 8; ++j) red[tm][tn * 8 + j] = part[j];
        __syncthreads();
        if (tid < TB_N) {
            float s = 0.f;
#pragma unroll
            for (int r = 0; r < 16; ++r) s += red[r][tid];  // fixed order: deterministic
            xacc[tid] += s;
        }
        __syncthreads();
    }

    if (tid < TB_N) g_xconv[(size_t)bl * F_ + n0 + tid] = xacc[tid];
}

// ============================================================================
// Kernel C: head MLP per (b,l): 384->128 gelu ->64 gelu ->1 ; pred * mask
// ============================================================================
__global__ void __launch_bounds__(128) head_kernel(
    const float* __restrict__ hw1, const float* __restrict__ hb1,
    const float* __restrict__ hw2, const float* __restrict__ hb2,
    const float* __restrict__ hw3, const float* __restrict__ hb3,
    const float* __restrict__ mask)
{
    const int bl  = blockIdx.x;
    const int tid = threadIdx.x;   // 128
    __shared__ float xs[F_];
    __shared__ float h1[H_];
    __shared__ float h2[H_ / 2];

    for (int i = tid; i < F_; i += 128) xs[i] = g_xconv[(size_t)bl * F_ + i];
    __syncthreads();

    float s = hb1[tid];
    for (int f = 0; f < F_; ++f) s += xs[f] * hw1[f * H_ + tid];  // coalesced over tid
    h1[tid] = gelu_f(s);
    __syncthreads();

    if (tid < 64) {
        float s2 = hb2[tid];
#pragma unroll 4
        for (int h = 0; h < H_; ++h) s2 += h1[h] * hw2[h * 64 + tid];
        h2[tid] = gelu_f(s2);
    }
    __syncthreads();

    if (tid == 0) {
        float p = hb3[0];
        for (int j = 0; j < 64; ++j) p += h2[j] * hw3[j];  // fixed order
        g_predm[bl] = p * mask[bl];
    }
}

// ============================================================================
// Kernel D: per-batch masked reduction: sum(pred*mask) / sqrt(clip(sum mask,1))
// ============================================================================
__global__ void __launch_bounds__(128) reduce_kernel(
    const float* __restrict__ mask, float* __restrict__ out)
{
    const int b   = blockIdx.x;    // 4 blocks
    const int tid = threadIdx.x;   // 128
    __shared__ float sp[128];
    __shared__ float sm[128];

    float p = 0.f, mk = 0.f;
    for (int l = tid; l < L_; l += 128) {
        p  += g_predm[b * L_ + l];
        mk += mask[b * L_ + l];
    }
    sp[tid] = p; sm[tid] = mk;
    __syncthreads();
    for (int s = 64; s > 0; s >>= 1) {
        if (tid < s) { sp[tid] += sp[tid + s]; sm[tid] += sm[tid + s]; }
        __syncthreads();
    }
    if (tid == 0) {
        float vl = sm[0] < 1.f ? 1.f : sm[0];
        out[b] = sp[0] / sqrtf(vl);
    }
}

// ============================================================================
// Launch
// ============================================================================
extern "C" void kernel_launch(void* const* d_in, const int* in_sizes, int n_in,
                              void* d_out, int out_size)
{
    const float* h_V  = (const float*)d_in[0];
    const float* h_E  = (const float*)d_in[1];
    const float* mask = (const float*)d_in[2];
    const float* fw1  = (const float*)d_in[3];
    const float* fb1  = (const float*)d_in[4];
    const float* fw2  = (const float*)d_in[5];
    const float* fb2  = (const float*)d_in[6];
    const float* hw1  = (const float*)d_in[7];
    const float* hb1  = (const float*)d_in[8];
    const float* hw2  = (const float*)d_in[9];
    const float* hb2  = (const float*)d_in[10];
    const float* hw3  = (const float*)d_in[11];
    const float* hb3  = (const float*)d_in[12];
    float* out = (float*)d_out;

    dim3 gA(M1_ / TA_M, F_ / TA_N);          // 9216 x 3
    gemm1_kernel<<<gA, 256>>>(h_E, fw1, fb1);

    dim3 gB(B_ * L_, F_ / TB_N);             // 1536 x 3
    gemm2_kernel<<<gB, 256>>>(fw2, fb2, h_V);

    head_kernel<<<B_ * L_, 128>>>(hw1, hb1, hw2, hb2, hw3, hb3, mask);

    reduce_kernel<<<B_, 128>>>(mask, out);
}

// round 4
// speedup vs baseline: 2.8230x; 2.8230x over previous
#include <cuda_runtime.h>
#include <math.h>
#include <stdint.h>

// ---------------------------------------------------------------------------
// Problem constants
// ---------------------------------------------------------------------------
#define B_  4
#define L_  384
#define H_  128
#define F_  384
#define M1_ (B_ * L_ * L_)      // 589824 edge rows

// ---------------------------------------------------------------------------
// Device scratch (allocation-free rule)
// ---------------------------------------------------------------------------
__device__ float g_T1[(size_t)M1_ * F_];        // gelu(h_E @ fw1 + fb1)
__device__ float g_xconv[(size_t)B_ * L_ * F_];
__device__ float g_predm[B_ * L_];
__device__ float g_fw1T[F_ * H_];               // [n=384][k=128]
__device__ float g_fw2T[F_ * F_];               // [n=384][k=384]

__device__ __forceinline__ float gelu_f(float x) {
    return 0.5f * x * (1.0f + erff(x * 0.70710678118654752440f));
}

__device__ __forceinline__ float tf32r(float x) {
    float y;
    asm("cvt.rna.tf32.f32 %0, %1;" : "=f"(y) : "f"(x));
    return y;
}

// m16n8k8 tf32 MMA (legacy tensor path; works on compute_103)
__device__ __forceinline__ void mma8(float* c, const uint32_t* a, uint32_t b0, uint32_t b1) {
    asm volatile(
        "mma.sync.aligned.m16n8k8.row.col.f32.tf32.tf32.f32 "
        "{%0,%1,%2,%3}, {%4,%5,%6,%7}, {%8,%9}, {%0,%1,%2,%3};"
        : "+f"(c[0]), "+f"(c[1]), "+f"(c[2]), "+f"(c[3])
        : "r"(a[0]), "r"(a[1]), "r"(a[2]), "r"(a[3]), "r"(b0), "r"(b1));
}

// Stage a [128 rows x 32 cols] fp32 block (gmem row stride ldg) into smem [128][36],
// rounding each value to tf32 (rna).
__device__ __forceinline__ void stage128x32(const float* __restrict__ g, int ldg,
                                            float (*S)[36], int tid) {
#pragma unroll
    for (int i = 0; i < 4; ++i) {
        int idx = tid + i * 256;
        int row = idx >> 3, q = idx & 7;
        float4 v = *reinterpret_cast<const float4*>(g + (size_t)row * ldg + q * 4);
        v.x = tf32r(v.x); v.y = tf32r(v.y); v.z = tf32r(v.z); v.w = tf32r(v.w);
        *reinterpret_cast<float4*>(&S[row][q * 4]) = v;
    }
}

// ---------------------------------------------------------------------------
// Kernel 0: transpose weights to [n][k] (B operand is .col = n-major rows of k)
// ---------------------------------------------------------------------------
__global__ void __launch_bounds__(256) transpose_w(const float* __restrict__ fw1,
                                                   const float* __restrict__ fw2) {
    int idx = blockIdx.x * 256 + threadIdx.x;
    if (idx < F_ * H_) {
        int n = idx / H_, k = idx % H_;
        g_fw1T[idx] = fw1[k * F_ + n];
    }
    int i2 = idx - F_ * H_;
    if (i2 >= 0 && i2 < F_ * F_) {
        int n = i2 / F_, k = i2 % F_;
        g_fw2T[i2] = fw2[k * F_ + n];
    }
}

// ---------------------------------------------------------------------------
// Kernel 1: T1 = gelu(h_E @ fw1 + fb1)
//   grid (M1/128, 3), block 256 (8 warps: wm = wid&3 over M, wn = wid>>2 over N)
//   CTA tile 128x128, warp tile 32x64, K = 128 in 4 chunks of 32.
// ---------------------------------------------------------------------------
__global__ void __launch_bounds__(256, 2) gemm1_mma(const float* __restrict__ hE,
                                                    const float* __restrict__ fb1) {
    __shared__ float As[128][36];
    __shared__ float Bs[128][36];
    __shared__ float biasS[128];

    const int tid = threadIdx.x;
    const int wid = tid >> 5, lane = tid & 31;
    const int gid = lane >> 2, tig = lane & 3;
    const int wm = wid & 3, wn = wid >> 2;
    const int m0 = blockIdx.x * 128, n0 = blockIdx.y * 128;

    if (tid < 128) biasS[tid] = fb1[n0 + tid];

    float acc[2][8][4];
#pragma unroll
    for (int mt = 0; mt < 2; ++mt)
#pragma unroll
        for (int nt = 0; nt < 8; ++nt)
#pragma unroll
            for (int j = 0; j < 4; ++j) acc[mt][nt][j] = 0.f;

    const uint32_t* Au = reinterpret_cast<const uint32_t*>(&As[0][0]);
    const uint32_t* Bu = reinterpret_cast<const uint32_t*>(&Bs[0][0]);

    for (int kc = 0; kc < 4; ++kc) {
        __syncthreads();
        stage128x32(hE + (size_t)m0 * H_ + kc * 32, H_, As, tid);
        stage128x32(g_fw1T + (size_t)n0 * H_ + kc * 32, H_, Bs, tid);   // FIXED: n0 offset
        __syncthreads();

#pragma unroll
        for (int ks = 0; ks < 4; ++ks) {
            const int kk = ks * 8;
            uint32_t bf[8][2];
#pragma unroll
            for (int nt = 0; nt < 8; ++nt) {
                int n = wn * 64 + nt * 8 + gid;
                bf[nt][0] = Bu[n * 36 + kk + tig];
                bf[nt][1] = Bu[n * 36 + kk + tig + 4];
            }
#pragma unroll
            for (int mt = 0; mt < 2; ++mt) {
                uint32_t af[4];
                int r = wm * 32 + mt * 16 + gid;
                af[0] = Au[r * 36 + kk + tig];
                af[1] = Au[(r + 8) * 36 + kk + tig];
                af[2] = Au[r * 36 + kk + tig + 4];
                af[3] = Au[(r + 8) * 36 + kk + tig + 4];
#pragma unroll
                for (int nt = 0; nt < 8; ++nt) mma8(acc[mt][nt], af, bf[nt][0], bf[nt][1]);
            }
        }
    }

    // Epilogue: bias + exact-erf gelu, float2 stores
#pragma unroll
    for (int mt = 0; mt < 2; ++mt)
#pragma unroll
        for (int nt = 0; nt < 8; ++nt) {
            float* c = acc[mt][nt];
            int lr = wm * 32 + mt * 16 + gid;
            int lc = wn * 64 + nt * 8 + 2 * tig;
            float b0v = biasS[lc], b1v = biasS[lc + 1];
            size_t base = (size_t)(m0 + lr) * F_ + n0 + lc;
            float2 v;
            v.x = gelu_f(c[0] + b0v); v.y = gelu_f(c[1] + b1v);
            *reinterpret_cast<float2*>(g_T1 + base) = v;
            v.x = gelu_f(c[2] + b0v); v.y = gelu_f(c[3] + b1v);
            *reinterpret_cast<float2*>(g_T1 + base + (size_t)8 * F_) = v;
        }
}

// ---------------------------------------------------------------------------
// Kernel 2: per (bl, n-tile): T2 = gelu(T1_bl @ fw2 + fb2);
//           xconv[bl, n] = sum_k hV[b,k,n] * T2[k,n]   (T2 never hits memory)
//   grid (1536, 3), block 256. 3 m-tiles of 128 k-edges, K = 384 in 12 chunks.
// ---------------------------------------------------------------------------
__global__ void __launch_bounds__(256, 2) gemm2_mma(const float* __restrict__ hV,
                                                    const float* __restrict__ fb2) {
    __shared__ float As[128][36];
    __shared__ float Bs[128][36];
    __shared__ float biasS[128];
    __shared__ float red[4][128];
    __shared__ float xacc[128];

    const int tid = threadIdx.x;
    const int wid = tid >> 5, lane = tid & 31;
    const int gid = lane >> 2, tig = lane & 3;
    const int wm = wid & 3, wn = wid >> 2;
    const int bl = blockIdx.x, b = bl / L_;
    const int n0 = blockIdx.y * 128;

    if (tid < 128) { biasS[tid] = fb2[n0 + tid]; xacc[tid] = 0.f; }

    const uint32_t* Au = reinterpret_cast<const uint32_t*>(&As[0][0]);
    const uint32_t* Bu = reinterpret_cast<const uint32_t*>(&Bs[0][0]);

    for (int mt = 0; mt < 3; ++mt) {
        float acc[2][8][4];
#pragma unroll
        for (int m2 = 0; m2 < 2; ++m2)
#pragma unroll
            for (int nt = 0; nt < 8; ++nt)
#pragma unroll
                for (int j = 0; j < 4; ++j) acc[m2][nt][j] = 0.f;

        const float* Abase = g_T1 + (size_t)(bl * L_ + mt * 128) * F_;

        for (int kc = 0; kc < 12; ++kc) {
            __syncthreads();
            stage128x32(Abase + kc * 32, F_, As, tid);
            stage128x32(g_fw2T + (size_t)n0 * F_ + kc * 32, F_, Bs, tid);
            __syncthreads();

#pragma unroll
            for (int ks = 0; ks < 4; ++ks) {
                const int kk = ks * 8;
                uint32_t bf[8][2];
#pragma unroll
                for (int nt = 0; nt < 8; ++nt) {
                    int n = wn * 64 + nt * 8 + gid;
                    bf[nt][0] = Bu[n * 36 + kk + tig];
                    bf[nt][1] = Bu[n * 36 + kk + tig + 4];
                }
#pragma unroll
                for (int m2 = 0; m2 < 2; ++m2) {
                    uint32_t af[4];
                    int r = wm * 32 + m2 * 16 + gid;
                    af[0] = Au[r * 36 + kk + tig];
                    af[1] = Au[(r + 8) * 36 + kk + tig];
                    af[2] = Au[r * 36 + kk + tig + 4];
                    af[3] = Au[(r + 8) * 36 + kk + tig + 4];
#pragma unroll
                    for (int nt = 0; nt < 8; ++nt) mma8(acc[m2][nt], af, bf[nt][0], bf[nt][1]);
                }
            }
        }

        // Fused epilogue: gelu + bias, * hV, reduce over the 128 k-edge rows
        float p0[8], p1[8];
#pragma unroll
        for (int nt = 0; nt < 8; ++nt) { p0[nt] = 0.f; p1[nt] = 0.f; }

#pragma unroll
        for (int m2 = 0; m2 < 2; ++m2)
#pragma unroll
            for (int nt = 0; nt < 8; ++nt) {
                float* c = acc[m2][nt];
                int r0 = wm * 32 + m2 * 16 + gid;
                int lc = wn * 64 + nt * 8 + 2 * tig;
                float b0v = biasS[lc], b1v = biasS[lc + 1];
                const float* hv0 = hV + ((size_t)b * L_ + mt * 128 + r0) * F_ + n0 + lc;
                float2 h0 = *reinterpret_cast<const float2*>(hv0);
                float2 h1 = *reinterpret_cast<const float2*>(hv0 + (size_t)8 * F_);
                p0[nt] += gelu_f(c[0] + b0v) * h0.x + gelu_f(c[2] + b0v) * h1.x;
                p1[nt] += gelu_f(c[1] + b1v) * h0.y + gelu_f(c[3] + b1v) * h1.y;
            }

        // butterfly over gid (lanes differ in bits 2..4)
#pragma unroll
        for (int nt = 0; nt < 8; ++nt) {
#pragma unroll
            for (int off = 16; off >= 4; off >>= 1) {
                p0[nt] += __shfl_xor_sync(0xFFFFFFFFu, p0[nt], off);
                p1[nt] += __shfl_xor_sync(0xFFFFFFFFu, p1[nt], off);
            }
        }
        if (gid == 0) {
#pragma unroll
            for (int nt = 0; nt < 8; ++nt) {
                red[wm][wn * 64 + nt * 8 + 2 * tig]     = p0[nt];
                red[wm][wn * 64 + nt * 8 + 2 * tig + 1] = p1[nt];
            }
        }
        __syncthreads();
        if (tid < 128)
            xacc[tid] += red[0][tid] + red[1][tid] + red[2][tid] + red[3][tid];
        // next mt's staging is separated from this read by the loop-head __syncthreads
    }

    __syncthreads();
    if (tid < 128) g_xconv[(size_t)bl * F_ + n0 + tid] = xacc[tid];
}

// ---------------------------------------------------------------------------
// Kernel 3: head MLP per (b,l): 384->128 gelu ->64 gelu ->1 ; pred * mask
// ---------------------------------------------------------------------------
__global__ void __launch_bounds__(128) head_kernel(
    const float* __restrict__ hw1, const float* __restrict__ hb1,
    const float* __restrict__ hw2, const float* __restrict__ hb2,
    const float* __restrict__ hw3, const float* __restrict__ hb3,
    const float* __restrict__ mask) {
    const int bl = blockIdx.x;
    const int tid = threadIdx.x;
    __shared__ float xs[F_];
    __shared__ float h1[H_];
    __shared__ float h2[H_ / 2];

    for (int i = tid; i < F_; i += 128) xs[i] = g_xconv[(size_t)bl * F_ + i];
    __syncthreads();

    float s = hb1[tid];
    for (int f = 0; f < F_; ++f) s += xs[f] * hw1[f * H_ + tid];
    h1[tid] = gelu_f(s);
    __syncthreads();

    if (tid < 64) {
        float s2 = hb2[tid];
#pragma unroll 4
        for (int h = 0; h < H_; ++h) s2 += h1[h] * hw2[h * 64 + tid];
        h2[tid] = gelu_f(s2);
    }
    __syncthreads();

    if (tid == 0) {
        float p = hb3[0];
        for (int j = 0; j < 64; ++j) p += h2[j] * hw3[j];
        g_predm[bl] = p * mask[bl];
    }
}

// ---------------------------------------------------------------------------
// Kernel 4: per-batch masked reduction
// ---------------------------------------------------------------------------
__global__ void __launch_bounds__(128) reduce_kernel(const float* __restrict__ mask,
                                                     float* __restrict__ out) {
    const int b = blockIdx.x;
    const int tid = threadIdx.x;
    __shared__ float sp[128];
    __shared__ float smk[128];

    float p = 0.f, mk = 0.f;
    for (int l = tid; l < L_; l += 128) {
        p += g_predm[b * L_ + l];
        mk += mask[b * L_ + l];
    }
    sp[tid] = p; smk[tid] = mk;
    __syncthreads();
    for (int s = 64; s > 0; s >>= 1) {
        if (tid < s) { sp[tid] += sp[tid + s]; smk[tid] += smk[tid + s]; }
        __syncthreads();
    }
    if (tid == 0) {
        float vl = smk[0] < 1.f ? 1.f : smk[0];
        out[b] = sp[0] / sqrtf(vl);
    }
}

// ---------------------------------------------------------------------------
// Launch
// ---------------------------------------------------------------------------
extern "C" void kernel_launch(void* const* d_in, const int* in_sizes, int n_in,
                              void* d_out, int out_size) {
    const float* h_V  = (const float*)d_in[0];
    const float* h_E  = (const float*)d_in[1];
    const float* mask = (const float*)d_in[2];
    const float* fw1  = (const float*)d_in[3];
    const float* fb1  = (const float*)d_in[4];
    const float* fw2  = (const float*)d_in[5];
    const float* fb2  = (const float*)d_in[6];
    const float* hw1  = (const float*)d_in[7];
    const float* hb1  = (const float*)d_in[8];
    const float* hw2  = (const float*)d_in[9];
    const float* hb2  = (const float*)d_in[10];
    const float* hw3  = (const float*)d_in[11];
    const float* hb3  = (const float*)d_in[12];
    float* out = (float*)d_out;

    transpose_w<<<(F_ * H_ + F_ * F_ + 255) / 256, 256>>>(fw1, fw2);

    dim3 g1(M1_ / 128, F_ / 128);            // 4608 x 3
    gemm1_mma<<<g1, 256>>>(h_E, fb1);

    dim3 g2(B_ * L_, F_ / 128);              // 1536 x 3
    gemm2_mma<<<g2, 256>>>(h_V, fb2);

    head_kernel<<<B_ * L_, 128>>>(hw1, hb1, hw2, hb2, hw3, hb3, mask);
    reduce_kernel<<<B_, 128>>>(mask, out);
}

// round 6
// speedup vs baseline: 3.1352x; 1.1106x over previous
#include <cuda_runtime.h>
#include <math.h>
#include <stdint.h>

// ---------------------------------------------------------------------------
// Problem constants
// ---------------------------------------------------------------------------
#define B_  4
#define L_  384
#define H_  128
#define F_  384
#define M1_ (B_ * L_ * L_)      // 589824 edge rows

// ---------------------------------------------------------------------------
// Device scratch (allocation-free rule)
// ---------------------------------------------------------------------------
__device__ float g_T1[(size_t)M1_ * F_];        // tf32-rounded gelu(h_E @ fw1 + fb1)
__device__ float g_xconv[(size_t)B_ * L_ * F_];
__device__ float g_predm[B_ * L_];
__device__ float g_fw1T[F_ * H_];               // [n=384][k=128], tf32-rounded
__device__ float g_fw2T[F_ * F_];               // [n=384][k=384], tf32-rounded

__device__ __forceinline__ float gelu_f(float x) {
    return 0.5f * x * (1.0f + erff(x * 0.70710678118654752440f));
}

__device__ __forceinline__ float tf32r(float x) {
    float y;
    asm("cvt.rna.tf32.f32 %0, %1;" : "=f"(y) : "f"(x));
    return y;
}

__device__ __forceinline__ uint32_t smem_u32(const void* p) {
    uint32_t a;
    asm("{ .reg .u64 t; cvta.to.shared.u64 t, %1; cvt.u32.u64 %0, t; }" : "=r"(a) : "l"(p));
    return a;
}

// m16n8k8 tf32 MMA. Operands must be pre-rounded (rna) tf32 bit patterns.
__device__ __forceinline__ void mma8(float* c, const uint32_t* a, uint32_t b0, uint32_t b1) {
    asm volatile(
        "mma.sync.aligned.m16n8k8.row.col.f32.tf32.tf32.f32 "
        "{%0,%1,%2,%3}, {%4,%5,%6,%7}, {%8,%9}, {%0,%1,%2,%3};"
        : "+f"(c[0]), "+f"(c[1]), "+f"(c[2]), "+f"(c[3])
        : "r"(a[0]), "r"(a[1]), "r"(a[2]), "r"(a[3]), "r"(b0), "r"(b1));
}

#define CP_COMMIT() asm volatile("cp.async.commit_group;" ::: "memory")
#define CP_WAIT1()  asm volatile("cp.async.wait_group 1;" ::: "memory")
#define CP_WAIT0()  asm volatile("cp.async.wait_group 0;" ::: "memory")

// Async-stage a [128 rows x 32 f32] block (gmem row stride ldg elems) into a
// smem buffer with row pitch 36 floats. 256 threads x 4 x 16B.
__device__ __forceinline__ void stage_async(const float* __restrict__ g, int ldg,
                                            uint32_t s_addr, int tid) {
#pragma unroll
    for (int i = 0; i < 4; ++i) {
        int idx = tid + i * 256;
        int row = idx >> 3, q = idx & 7;
        uint32_t dst = s_addr + (uint32_t)(row * 36 + q * 4) * 4u;
        const float* src = g + (size_t)row * ldg + q * 4;
        asm volatile("cp.async.cg.shared.global [%0], [%1], 16;" :: "r"(dst), "l"(src));
    }
}

// ---------------------------------------------------------------------------
// Dynamic smem layout (bytes)
// ---------------------------------------------------------------------------
#define SB_   18432                 // one 128x36 f32 buffer
#define O_A   0                     // 2 buffers
#define O_B   (2 * SB_)             // 2 buffers
#define O_BIAS (4 * SB_)            // 512 B
#define O_RED  (O_BIAS + 512)       // 2048 B (gemm2)
#define O_XACC (O_RED + 2048)       // 512 B  (gemm2)
#define SMEM1  (O_BIAS + 512)
#define SMEM2  (O_XACC + 512)

// ---------------------------------------------------------------------------
// Kernel 0: transpose weights to [n][k], rounding to tf32 (rna)
// ---------------------------------------------------------------------------
__global__ void __launch_bounds__(256) transpose_w(const float* __restrict__ fw1,
                                                   const float* __restrict__ fw2) {
    int idx = blockIdx.x * 256 + threadIdx.x;
    if (idx < F_ * H_) {
        int n = idx / H_, k = idx % H_;
        g_fw1T[idx] = tf32r(fw1[k * F_ + n]);
    }
    int i2 = idx - F_ * H_;
    if (i2 >= 0 && i2 < F_ * F_) {
        int n = i2 / F_, k = i2 % F_;
        g_fw2T[i2] = tf32r(fw2[k * F_ + n]);
    }
}

// ---------------------------------------------------------------------------
// Warp-level MMA block over one staged K=32 chunk.
// CVT_A: round A fragments to tf32 in registers (gemm1: raw h_E in smem).
// ---------------------------------------------------------------------------
template <bool CVT_A>
__device__ __forceinline__ void mma_chunk(const uint32_t* Au, const uint32_t* Bu,
                                          float acc[2][8][4], int wm, int wn,
                                          int gid, int tig) {
#pragma unroll
    for (int ks = 0; ks < 4; ++ks) {
        const int kk = ks * 8;
        uint32_t bf[8][2];
#pragma unroll
        for (int nt = 0; nt < 8; ++nt) {
            int n = wn * 64 + nt * 8 + gid;
            bf[nt][0] = Bu[n * 36 + kk + tig];
            bf[nt][1] = Bu[n * 36 + kk + tig + 4];
        }
#pragma unroll
        for (int mt = 0; mt < 2; ++mt) {
            uint32_t af[4];
            int r = wm * 32 + mt * 16 + gid;
            af[0] = Au[r * 36 + kk + tig];
            af[1] = Au[(r + 8) * 36 + kk + tig];
            af[2] = Au[r * 36 + kk + tig + 4];
            af[3] = Au[(r + 8) * 36 + kk + tig + 4];
            if (CVT_A) {
#pragma unroll
                for (int j = 0; j < 4; ++j)
                    af[j] = __float_as_uint(tf32r(__uint_as_float(af[j])));
            }
#pragma unroll
            for (int nt = 0; nt < 8; ++nt) mma8(acc[mt][nt], af, bf[nt][0], bf[nt][1]);
        }
    }
}

// ---------------------------------------------------------------------------
// Kernel 1: T1 = tf32r(gelu(h_E @ fw1 + fb1))
//   grid (4608, 3), block 256. CTA tile 128x128, warp tile 32x64.
//   K=128 in 4 chunks of 32, cp.async double-buffered. A fragments cvt'd.
// ---------------------------------------------------------------------------
__global__ void __launch_bounds__(256, 2) gemm1_mma(const float* __restrict__ hE,
                                                    const float* __restrict__ fb1) {
    extern __shared__ char smc[];
    const uint32_t sb = smem_u32(smc);
    float* biasS = reinterpret_cast<float*>(smc + O_BIAS);

    const int tid = threadIdx.x;
    const int wid = tid >> 5, lane = tid & 31;
    const int gid = lane >> 2, tig = lane & 3;
    const int wm = wid & 3, wn = wid >> 2;
    const int m0 = blockIdx.x * 128, n0 = blockIdx.y * 128;

    if (tid < 128) biasS[tid] = fb1[n0 + tid];

    float acc[2][8][4];
#pragma unroll
    for (int mt = 0; mt < 2; ++mt)
#pragma unroll
        for (int nt = 0; nt < 8; ++nt)
#pragma unroll
            for (int j = 0; j < 4; ++j) acc[mt][nt][j] = 0.f;

    const float* Abase = hE + (size_t)m0 * H_;
    const float* Bbase = g_fw1T + (size_t)n0 * H_;

    stage_async(Abase, H_, sb + O_A, tid);
    stage_async(Bbase, H_, sb + O_B, tid);
    CP_COMMIT();

    for (int kc = 0; kc < 4; ++kc) {
        const int cur = kc & 1;
        if (kc + 1 < 4) {
            stage_async(Abase + (kc + 1) * 32, H_, sb + O_A + (1 - cur) * SB_, tid);
            stage_async(Bbase + (kc + 1) * 32, H_, sb + O_B + (1 - cur) * SB_, tid);
            CP_COMMIT();
            CP_WAIT1();
        } else {
            CP_WAIT0();
        }
        __syncthreads();

        const uint32_t* Au = reinterpret_cast<const uint32_t*>(smc + O_A + cur * SB_);
        const uint32_t* Bu = reinterpret_cast<const uint32_t*>(smc + O_B + cur * SB_);
        mma_chunk<true>(Au, Bu, acc, wm, wn, gid, tig);
        __syncthreads();
    }

    // Epilogue: bias + exact-erf gelu, round to tf32 (rna), float2 stores.
    // The rounding makes GEMM2's A operand cvt-free with full rna semantics.
#pragma unroll
    for (int mt = 0; mt < 2; ++mt)
#pragma unroll
        for (int nt = 0; nt < 8; ++nt) {
            float* c = acc[mt][nt];
            int lr = wm * 32 + mt * 16 + gid;
            int lc = wn * 64 + nt * 8 + 2 * tig;
            float b0v = biasS[lc], b1v = biasS[lc + 1];
            size_t base = (size_t)(m0 + lr) * F_ + n0 + lc;
            float2 v;
            v.x = tf32r(gelu_f(c[0] + b0v)); v.y = tf32r(gelu_f(c[1] + b1v));
            *reinterpret_cast<float2*>(g_T1 + base) = v;
            v.x = tf32r(gelu_f(c[2] + b0v)); v.y = tf32r(gelu_f(c[3] + b1v));
            *reinterpret_cast<float2*>(g_T1 + base + (size_t)8 * F_) = v;
        }
}

// ---------------------------------------------------------------------------
// Kernel 2: per (bl, n-tile): T2 = gelu(T1_bl @ fw2 + fb2);
//           xconv[bl, n] = sum_k hV[b,k,n] * T2[k,n]   (T2 never hits memory)
//   grid (1536, 3), block 256. 3 m-tiles, K=384 in 12 chunks, cp.async
//   double-buffered. Both operands pre-rounded -> no in-loop cvts.
// ---------------------------------------------------------------------------
__global__ void __launch_bounds__(256, 2) gemm2_mma(const float* __restrict__ hV,
                                                    const float* __restrict__ fb2) {
    extern __shared__ char smc[];
    const uint32_t sb = smem_u32(smc);
    float* biasS = reinterpret_cast<float*>(smc + O_BIAS);
    float (*red)[128] = reinterpret_cast<float (*)[128]>(smc + O_RED);
    float* xacc = reinterpret_cast<float*>(smc + O_XACC);

    const int tid = threadIdx.x;
    const int wid = tid >> 5, lane = tid & 31;
    const int gid = lane >> 2, tig = lane & 3;
    const int wm = wid & 3, wn = wid >> 2;
    const int bl = blockIdx.x, b = bl / L_;
    const int n0 = blockIdx.y * 128;

    if (tid < 128) { biasS[tid] = fb2[n0 + tid]; xacc[tid] = 0.f; }

    const float* Bbase = g_fw2T + (size_t)n0 * F_;

    for (int mt = 0; mt < 3; ++mt) {
        float acc[2][8][4];
#pragma unroll
        for (int m2 = 0; m2 < 2; ++m2)
#pragma unroll
            for (int nt = 0; nt < 8; ++nt)
#pragma unroll
                for (int j = 0; j < 4; ++j) acc[m2][nt][j] = 0.f;

        const float* Abase = g_T1 + (size_t)(bl * L_ + mt * 128) * F_;

        stage_async(Abase, F_, sb + O_A, tid);
        stage_async(Bbase, F_, sb + O_B, tid);
        CP_COMMIT();

        for (int kc = 0; kc < 12; ++kc) {
            const int cur = kc & 1;
            if (kc + 1 < 12) {
                stage_async(Abase + (kc + 1) * 32, F_, sb + O_A + (1 - cur) * SB_, tid);
                stage_async(Bbase + (kc + 1) * 32, F_, sb + O_B + (1 - cur) * SB_, tid);
                CP_COMMIT();
                CP_WAIT1();
            } else {
                CP_WAIT0();
            }
            __syncthreads();

            const uint32_t* Au = reinterpret_cast<const uint32_t*>(smc + O_A + cur * SB_);
            const uint32_t* Bu = reinterpret_cast<const uint32_t*>(smc + O_B + cur * SB_);
            mma_chunk<false>(Au, Bu, acc, wm, wn, gid, tig);
            __syncthreads();
        }

        // Fused epilogue: gelu + bias, * hV, reduce over the 128 k-edge rows
        float p0[8], p1[8];
#pragma unroll
        for (int nt = 0; nt < 8; ++nt) { p0[nt] = 0.f; p1[nt] = 0.f; }

#pragma unroll
        for (int m2 = 0; m2 < 2; ++m2)
#pragma unroll
            for (int nt = 0; nt < 8; ++nt) {
                float* c = acc[m2][nt];
                int r0 = wm * 32 + m2 * 16 + gid;
                int lc = wn * 64 + nt * 8 + 2 * tig;
                float b0v = biasS[lc], b1v = biasS[lc + 1];
                const float* hv0 = hV + ((size_t)b * L_ + mt * 128 + r0) * F_ + n0 + lc;
                float2 h0 = *reinterpret_cast<const float2*>(hv0);
                float2 h1 = *reinterpret_cast<const float2*>(hv0 + (size_t)8 * F_);
                p0[nt] += gelu_f(c[0] + b0v) * h0.x + gelu_f(c[2] + b0v) * h1.x;
                p1[nt] += gelu_f(c[1] + b1v) * h0.y + gelu_f(c[3] + b1v) * h1.y;
            }

        // butterfly over gid (lanes differ in bits 2..4)
#pragma unroll
        for (int nt = 0; nt < 8; ++nt) {
#pragma unroll
            for (int off = 16; off >= 4; off >>= 1) {
                p0[nt] += __shfl_xor_sync(0xFFFFFFFFu, p0[nt], off);
                p1[nt] += __shfl_xor_sync(0xFFFFFFFFu, p1[nt], off);
            }
        }
        if (gid == 0) {
#pragma unroll
            for (int nt = 0; nt < 8; ++nt) {
                red[wm][wn * 64 + nt * 8 + 2 * tig]     = p0[nt];
                red[wm][wn * 64 + nt * 8 + 2 * tig + 1] = p1[nt];
            }
        }
        __syncthreads();
        if (tid < 128)
            xacc[tid] += red[0][tid] + red[1][tid] + red[2][tid] + red[3][tid];
        __syncthreads();
    }

    if (tid < 128) g_xconv[(size_t)bl * F_ + n0 + tid] = xacc[tid];
}

// ---------------------------------------------------------------------------
// Kernel 3: head MLP per (b,l): 384->128 gelu ->64 gelu ->1 ; pred * mask
// ---------------------------------------------------------------------------
__global__ void __launch_bounds__(128) head_kernel(
    const float* __restrict__ hw1, const float* __restrict__ hb1,
    const float* __restrict__ hw2, const float* __restrict__ hb2,
    const float* __restrict__ hw3, const float* __restrict__ hb3,
    const float* __restrict__ mask) {
    const int bl = blockIdx.x;
    const int tid = threadIdx.x;
    __shared__ float xs[F_];
    __shared__ float h1[H_];
    __shared__ float h2[H_ / 2];

    for (int i = tid; i < F_; i += 128) xs[i] = g_xconv[(size_t)bl * F_ + i];
    __syncthreads();

    float s = hb1[tid];
    for (int f = 0; f < F_; ++f) s += xs[f] * hw1[f * H_ + tid];
    h1[tid] = gelu_f(s);
    __syncthreads();

    if (tid < 64) {
        float s2 = hb2[tid];
#pragma unroll 4
        for (int h = 0; h < H_; ++h) s2 += h1[h] * hw2[h * 64 + tid];
        h2[tid] = gelu_f(s2);
    }
    __syncthreads();

    if (tid == 0) {
        float p = hb3[0];
        for (int j = 0; j < 64; ++j) p += h2[j] * hw3[j];
        g_predm[bl] = p * mask[bl];
    }
}

// ---------------------------------------------------------------------------
// Kernel 4: per-batch masked reduction
// ---------------------------------------------------------------------------
__global__ void __launch_bounds__(128) reduce_kernel(const float* __restrict__ mask,
                                                     float* __restrict__ out) {
    const int b = blockIdx.x;
    const int tid = threadIdx.x;
    __shared__ float sp[128];
    __shared__ float smk[128];

    float p = 0.f, mk = 0.f;
    for (int l = tid; l < L_; l += 128) {
        p += g_predm[b * L_ + l];
        mk += mask[b * L_ + l];
    }
    sp[tid] = p; smk[tid] = mk;
    __syncthreads();
    for (int s = 64; s > 0; s >>= 1) {
        if (tid < s) { sp[tid] += sp[tid + s]; smk[tid] += smk[tid + s]; }
        __syncthreads();
    }
    if (tid == 0) {
        float vl = smk[0] < 1.f ? 1.f : smk[0];
        out[b] = sp[0] / sqrtf(vl);
    }
}

// ---------------------------------------------------------------------------
// Launch
// ---------------------------------------------------------------------------
extern "C" void kernel_launch(void* const* d_in, const int* in_sizes, int n_in,
                              void* d_out, int out_size) {
    const float* h_V  = (const float*)d_in[0];
    const float* h_E  = (const float*)d_in[1];
    const float* mask = (const float*)d_in[2];
    const float* fw1  = (const float*)d_in[3];
    const float* fb1  = (const float*)d_in[4];
    const float* fw2  = (const float*)d_in[5];
    const float* fb2  = (const float*)d_in[6];
    const float* hw1  = (const float*)d_in[7];
    const float* hb1  = (const float*)d_in[8];
    const float* hw2  = (const float*)d_in[9];
    const float* hb2  = (const float*)d_in[10];
    const float* hw3  = (const float*)d_in[11];
    const float* hb3  = (const float*)d_in[12];
    float* out = (float*)d_out;

    static int configured = 0;
    if (!configured) {
        cudaFuncSetAttribute(gemm1_mma, cudaFuncAttributeMaxDynamicSharedMemorySize, SMEM1);
        cudaFuncSetAttribute(gemm2_mma, cudaFuncAttributeMaxDynamicSharedMemorySize, SMEM2);
        configured = 1;
    }

    transpose_w<<<(F_ * H_ + F_ * F_ + 255) / 256, 256>>>(fw1, fw2);

    dim3 g1(M1_ / 128, F_ / 128);            // 4608 x 3
    gemm1_mma<<<g1, 256, SMEM1>>>(h_E, fb1);

    dim3 g2(B_ * L_, F_ / 128);              // 1536 x 3
    gemm2_mma<<<g2, 256, SMEM2>>>(h_V, fb2);

    head_kernel<<<B_ * L_, 128>>>(hw1, hb1, hw2, hb2, hw3, hb3, mask);
    reduce_kernel<<<B_, 128>>>(mask, out);
}

// round 7
// speedup vs baseline: 3.1523x; 1.0055x over previous
#include <cuda_runtime.h>
#include <math.h>
#include <stdint.h>

// ---------------------------------------------------------------------------
// Problem constants
// ---------------------------------------------------------------------------
#define B_  4
#define L_  384
#define H_  128
#define F_  384
#define M1_ (B_ * L_ * L_)      // 589824 edge rows

// ---------------------------------------------------------------------------
// Device scratch (allocation-free rule)
// ---------------------------------------------------------------------------
__device__ float g_T1[(size_t)M1_ * F_];        // tf32-rounded gelu(h_E @ fw1 + fb1)
__device__ float g_xconv[(size_t)B_ * L_ * F_];
__device__ float g_predm[B_ * L_];
__device__ float g_fw1T[F_ * H_];               // [n=384][k=128], tf32-rounded
__device__ float g_fw2T[F_ * F_];               // [n=384][k=384], tf32-rounded

__device__ __forceinline__ float gelu_f(float x) {
    return 0.5f * x * (1.0f + erff(x * 0.70710678118654752440f));
}

__device__ __forceinline__ float tf32r(float x) {
    float y;
    asm("cvt.rna.tf32.f32 %0, %1;" : "=f"(y) : "f"(x));
    return y;
}

__device__ __forceinline__ uint32_t smem_u32(const void* p) {
    uint32_t a;
    asm("{ .reg .u64 t; cvta.to.shared.u64 t, %1; cvt.u32.u64 %0, t; }" : "=r"(a) : "l"(p));
    return a;
}

// m16n8k8 tf32 MMA. Operands must be pre-rounded (rna) tf32 bit patterns.
__device__ __forceinline__ void mma8(float* c, const uint32_t* a, uint32_t b0, uint32_t b1) {
    asm volatile(
        "mma.sync.aligned.m16n8k8.row.col.f32.tf32.tf32.f32 "
        "{%0,%1,%2,%3}, {%4,%5,%6,%7}, {%8,%9}, {%0,%1,%2,%3};"
        : "+f"(c[0]), "+f"(c[1]), "+f"(c[2]), "+f"(c[3])
        : "r"(a[0]), "r"(a[1]), "r"(a[2]), "r"(a[3]), "r"(b0), "r"(b1));
}

#define CP_COMMIT() asm volatile("cp.async.commit_group;" ::: "memory")
#define CP_WAIT1()  asm volatile("cp.async.wait_group 1;" ::: "memory")
#define CP_WAIT0()  asm volatile("cp.async.wait_group 0;" ::: "memory")

// Async-stage a [128 rows x 32 f32] block (gmem row stride ldg elems) into a
// smem buffer with row pitch 36 floats. 256 threads x 4 x 16B.
__device__ __forceinline__ void stage_async(const float* __restrict__ g, int ldg,
                                            uint32_t s_addr, int tid) {
#pragma unroll
    for (int i = 0; i < 4; ++i) {
        int idx = tid + i * 256;
        int row = idx >> 3, q = idx & 7;
        uint32_t dst = s_addr + (uint32_t)(row * 36 + q * 4) * 4u;
        const float* src = g + (size_t)row * ldg + q * 4;
        asm volatile("cp.async.cg.shared.global [%0], [%1], 16;" :: "r"(dst), "l"(src));
    }
}

// ---------------------------------------------------------------------------
// Dynamic smem layout (bytes)
// ---------------------------------------------------------------------------
#define SB_   18432                 // one 128x36 f32 buffer
#define O_A   0                     // 2 buffers
#define O_B   (2 * SB_)             // 2 buffers
#define O_BIAS (4 * SB_)            // 512 B
#define O_RED  (O_BIAS + 512)       // 2048 B (gemm2)
#define O_XACC (O_RED + 2048)       // 512 B  (gemm2)
#define SMEM1  (O_BIAS + 512)
#define SMEM2  (O_XACC + 512)

// ---------------------------------------------------------------------------
// Kernel 0: transpose weights to [n][k], rounding to tf32 (rna)
// ---------------------------------------------------------------------------
__global__ void __launch_bounds__(256) transpose_w(const float* __restrict__ fw1,
                                                   const float* __restrict__ fw2) {
    int idx = blockIdx.x * 256 + threadIdx.x;
    if (idx < F_ * H_) {
        int n = idx / H_, k = idx % H_;
        g_fw1T[idx] = tf32r(fw1[k * F_ + n]);
    }
    int i2 = idx - F_ * H_;
    if (i2 >= 0 && i2 < F_ * F_) {
        int n = i2 / F_, k = i2 % F_;
        g_fw2T[i2] = tf32r(fw2[k * F_ + n]);
    }
}

// ---------------------------------------------------------------------------
// Warp-level MMA block over one staged K=32 chunk.
// CVT_A: round A fragments to tf32 in registers (gemm1: raw h_E in smem).
// ---------------------------------------------------------------------------
template <bool CVT_A>
__device__ __forceinline__ void mma_chunk(const uint32_t* Au, const uint32_t* Bu,
                                          float acc[2][8][4], int wm, int wn,
                                          int gid, int tig) {
#pragma unroll
    for (int ks = 0; ks < 4; ++ks) {
        const int kk = ks * 8;
        uint32_t bf[8][2];
#pragma unroll
        for (int nt = 0; nt < 8; ++nt) {
            int n = wn * 64 + nt * 8 + gid;
            bf[nt][0] = Bu[n * 36 + kk + tig];
            bf[nt][1] = Bu[n * 36 + kk + tig + 4];
        }
#pragma unroll
        for (int mt = 0; mt < 2; ++mt) {
            uint32_t af[4];
            int r = wm * 32 + mt * 16 + gid;
            af[0] = Au[r * 36 + kk + tig];
            af[1] = Au[(r + 8) * 36 + kk + tig];
            af[2] = Au[r * 36 + kk + tig + 4];
            af[3] = Au[(r + 8) * 36 + kk + tig + 4];
            if (CVT_A) {
#pragma unroll
                for (int j = 0; j < 4; ++j)
                    af[j] = __float_as_uint(tf32r(__uint_as_float(af[j])));
            }
#pragma unroll
            for (int nt = 0; nt < 8; ++nt) mma8(acc[mt][nt], af, bf[nt][0], bf[nt][1]);
        }
    }
}

// ---------------------------------------------------------------------------
// Kernel 1: T1 = tf32r(gelu(h_E @ fw1 + fb1))
//   grid (3, 4608): x = n-tile (FAST axis) so the 3 CTAs sharing one A tile
//   are launch-adjacent -> A tile read once from DRAM, twice from L2.
//   CTA tile 128x128, warp tile 32x64. K=128 in 4 chunks, cp.async 2-buffer.
// ---------------------------------------------------------------------------
__global__ void __launch_bounds__(256, 2) gemm1_mma(const float* __restrict__ hE,
                                                    const float* __restrict__ fb1) {
    extern __shared__ char smc[];
    const uint32_t sb = smem_u32(smc);
    float* biasS = reinterpret_cast<float*>(smc + O_BIAS);

    const int tid = threadIdx.x;
    const int wid = tid >> 5, lane = tid & 31;
    const int gid = lane >> 2, tig = lane & 3;
    const int wm = wid & 3, wn = wid >> 2;
    const int m0 = blockIdx.y * 128, n0 = blockIdx.x * 128;   // swapped axes

    if (tid < 128) biasS[tid] = fb1[n0 + tid];

    float acc[2][8][4];
#pragma unroll
    for (int mt = 0; mt < 2; ++mt)
#pragma unroll
        for (int nt = 0; nt < 8; ++nt)
#pragma unroll
            for (int j = 0; j < 4; ++j) acc[mt][nt][j] = 0.f;

    const float* Abase = hE + (size_t)m0 * H_;
    const float* Bbase = g_fw1T + (size_t)n0 * H_;

    stage_async(Abase, H_, sb + O_A, tid);
    stage_async(Bbase, H_, sb + O_B, tid);
    CP_COMMIT();

    for (int kc = 0; kc < 4; ++kc) {
        const int cur = kc & 1;
        if (kc + 1 < 4) {
            stage_async(Abase + (kc + 1) * 32, H_, sb + O_A + (1 - cur) * SB_, tid);
            stage_async(Bbase + (kc + 1) * 32, H_, sb + O_B + (1 - cur) * SB_, tid);
            CP_COMMIT();
            CP_WAIT1();
        } else {
            CP_WAIT0();
        }
        __syncthreads();

        const uint32_t* Au = reinterpret_cast<const uint32_t*>(smc + O_A + cur * SB_);
        const uint32_t* Bu = reinterpret_cast<const uint32_t*>(smc + O_B + cur * SB_);
        mma_chunk<true>(Au, Bu, acc, wm, wn, gid, tig);
        __syncthreads();
    }

    // Epilogue: bias + exact-erf gelu, round to tf32 (rna), float2 stores.
#pragma unroll
    for (int mt = 0; mt < 2; ++mt)
#pragma unroll
        for (int nt = 0; nt < 8; ++nt) {
            float* c = acc[mt][nt];
            int lr = wm * 32 + mt * 16 + gid;
            int lc = wn * 64 + nt * 8 + 2 * tig;
            float b0v = biasS[lc], b1v = biasS[lc + 1];
            size_t base = (size_t)(m0 + lr) * F_ + n0 + lc;
            float2 v;
            v.x = tf32r(gelu_f(c[0] + b0v)); v.y = tf32r(gelu_f(c[1] + b1v));
            *reinterpret_cast<float2*>(g_T1 + base) = v;
            v.x = tf32r(gelu_f(c[2] + b0v)); v.y = tf32r(gelu_f(c[3] + b1v));
            *reinterpret_cast<float2*>(g_T1 + base + (size_t)8 * F_) = v;
        }
}

// ---------------------------------------------------------------------------
// Kernel 2: per (bl, n-tile): T2 = gelu(T1_bl @ fw2 + fb2);
//           xconv[bl, n] = sum_k hV[b,k,n] * T2[k,n]   (T2 never hits memory)
//   grid (3, 1536): x = n-tile (FAST axis) -> the 3 CTAs sharing one bl's T1
//   rows are launch-adjacent -> T1 read once from DRAM instead of 3x.
//   3 m-tiles, K=384 in 12 chunks, cp.async double-buffered.
// ---------------------------------------------------------------------------
__global__ void __launch_bounds__(256, 2) gemm2_mma(const float* __restrict__ hV,
                                                    const float* __restrict__ fb2) {
    extern __shared__ char smc[];
    const uint32_t sb = smem_u32(smc);
    float* biasS = reinterpret_cast<float*>(smc + O_BIAS);
    float (*red)[128] = reinterpret_cast<float (*)[128]>(smc + O_RED);
    float* xacc = reinterpret_cast<float*>(smc + O_XACC);

    const int tid = threadIdx.x;
    const int wid = tid >> 5, lane = tid & 31;
    const int gid = lane >> 2, tig = lane & 3;
    const int wm = wid & 3, wn = wid >> 2;
    const int bl = blockIdx.y, b = bl / L_;                   // swapped axes
    const int n0 = blockIdx.x * 128;

    if (tid < 128) { biasS[tid] = fb2[n0 + tid]; xacc[tid] = 0.f; }

    const float* Bbase = g_fw2T + (size_t)n0 * F_;

    for (int mt = 0; mt < 3; ++mt) {
        float acc[2][8][4];
#pragma unroll
        for (int m2 = 0; m2 < 2; ++m2)
#pragma unroll
            for (int nt = 0; nt < 8; ++nt)
#pragma unroll
                for (int j = 0; j < 4; ++j) acc[m2][nt][j] = 0.f;

        const float* Abase = g_T1 + (size_t)(bl * L_ + mt * 128) * F_;

        stage_async(Abase, F_, sb + O_A, tid);
        stage_async(Bbase, F_, sb + O_B, tid);
        CP_COMMIT();

        for (int kc = 0; kc < 12; ++kc) {
            const int cur = kc & 1;
            if (kc + 1 < 12) {
                stage_async(Abase + (kc + 1) * 32, F_, sb + O_A + (1 - cur) * SB_, tid);
                stage_async(Bbase + (kc + 1) * 32, F_, sb + O_B + (1 - cur) * SB_, tid);
                CP_COMMIT();
                CP_WAIT1();
            } else {
                CP_WAIT0();
            }
            __syncthreads();

            const uint32_t* Au = reinterpret_cast<const uint32_t*>(smc + O_A + cur * SB_);
            const uint32_t* Bu = reinterpret_cast<const uint32_t*>(smc + O_B + cur * SB_);
            mma_chunk<false>(Au, Bu, acc, wm, wn, gid, tig);
            __syncthreads();
        }

        // Fused epilogue: gelu + bias, * hV, reduce over the 128 k-edge rows
        float p0[8], p1[8];
#pragma unroll
        for (int nt = 0; nt < 8; ++nt) { p0[nt] = 0.f; p1[nt] = 0.f; }

#pragma unroll
        for (int m2 = 0; m2 < 2; ++m2)
#pragma unroll
            for (int nt = 0; nt < 8; ++nt) {
                float* c = acc[m2][nt];
                int r0 = wm * 32 + m2 * 16 + gid;
                int lc = wn * 64 + nt * 8 + 2 * tig;
                float b0v = biasS[lc], b1v = biasS[lc + 1];
                const float* hv0 = hV + ((size_t)b * L_ + mt * 128 + r0) * F_ + n0 + lc;
                float2 h0 = *reinterpret_cast<const float2*>(hv0);
                float2 h1 = *reinterpret_cast<const float2*>(hv0 + (size_t)8 * F_);
                p0[nt] += gelu_f(c[0] + b0v) * h0.x + gelu_f(c[2] + b0v) * h1.x;
                p1[nt] += gelu_f(c[1] + b1v) * h0.y + gelu_f(c[3] + b1v) * h1.y;
            }

        // butterfly over gid (lanes differ in bits 2..4)
#pragma unroll
        for (int nt = 0; nt < 8; ++nt) {
#pragma unroll
            for (int off = 16; off >= 4; off >>= 1) {
                p0[nt] += __shfl_xor_sync(0xFFFFFFFFu, p0[nt], off);
                p1[nt] += __shfl_xor_sync(0xFFFFFFFFu, p1[nt], off);
            }
        }
        if (gid == 0) {
#pragma unroll
            for (int nt = 0; nt < 8; ++nt) {
                red[wm][wn * 64 + nt * 8 + 2 * tig]     = p0[nt];
                red[wm][wn * 64 + nt * 8 + 2 * tig + 1] = p1[nt];
            }
        }
        __syncthreads();
        if (tid < 128)
            xacc[tid] += red[0][tid] + red[1][tid] + red[2][tid] + red[3][tid];
        __syncthreads();
    }

    if (tid < 128) g_xconv[(size_t)bl * F_ + n0 + tid] = xacc[tid];
}

// ---------------------------------------------------------------------------
// Kernel 3: head MLP per (b,l): 384->128 gelu ->64 gelu ->1 ; pred * mask
// ---------------------------------------------------------------------------
__global__ void __launch_bounds__(128) head_kernel(
    const float* __restrict__ hw1, const float* __restrict__ hb1,
    const float* __restrict__ hw2, const float* __restrict__ hb2,
    const float* __restrict__ hw3, const float* __restrict__ hb3,
    const float* __restrict__ mask) {
    const int bl = blockIdx.x;
    const int tid = threadIdx.x;
    __shared__ float xs[F_];
    __shared__ float h1[H_];
    __shared__ float h2[H_ / 2];

    for (int i = tid; i < F_; i += 128) xs[i] = g_xconv[(size_t)bl * F_ + i];
    __syncthreads();

    float s = hb1[tid];
    for (int f = 0; f < F_; ++f) s += xs[f] * hw1[f * H_ + tid];
    h1[tid] = gelu_f(s);
    __syncthreads();

    if (tid < 64) {
        float s2 = hb2[tid];
#pragma unroll 4
        for (int h = 0; h < H_; ++h) s2 += h1[h] * hw2[h * 64 + tid];
        h2[tid] = gelu_f(s2);
    }
    __syncthreads();

    if (tid == 0) {
        float p = hb3[0];
        for (int j = 0; j < 64; ++j) p += h2[j] * hw3[j];
        g_predm[bl] = p * mask[bl];
    }
}

// ---------------------------------------------------------------------------
// Kernel 4: per-batch masked reduction
// ---------------------------------------------------------------------------
__global__ void __launch_bounds__(128) reduce_kernel(const float* __restrict__ mask,
                                                     float* __restrict__ out) {
    const int b = blockIdx.x;
    const int tid = threadIdx.x;
    __shared__ float sp[128];
    __shared__ float smk[128];

    float p = 0.f, mk = 0.f;
    for (int l = tid; l < L_; l += 128) {
        p += g_predm[b * L_ + l];
        mk += mask[b * L_ + l];
    }
    sp[tid] = p; smk[tid] = mk;
    __syncthreads();
    for (int s = 64; s > 0; s >>= 1) {
        if (tid < s) { sp[tid] += sp[tid + s]; smk[tid] += smk[tid + s]; }
        __syncthreads();
    }
    if (tid == 0) {
        float vl = smk[0] < 1.f ? 1.f : smk[0];
        out[b] = sp[0] / sqrtf(vl);
    }
}

// ---------------------------------------------------------------------------
// Launch
// ---------------------------------------------------------------------------
extern "C" void kernel_launch(void* const* d_in, const int* in_sizes, int n_in,
                              void* d_out, int out_size) {
    const float* h_V  = (const float*)d_in[0];
    const float* h_E  = (const float*)d_in[1];
    const float* mask = (const float*)d_in[2];
    const float* fw1  = (const float*)d_in[3];
    const float* fb1  = (const float*)d_in[4];
    const float* fw2  = (const float*)d_in[5];
    const float* fb2  = (const float*)d_in[6];
    const float* hw1  = (const float*)d_in[7];
    const float* hb1  = (const float*)d_in[8];
    const float* hw2  = (const float*)d_in[9];
    const float* hb2  = (const float*)d_in[10];
    const float* hw3  = (const float*)d_in[11];
    const float* hb3  = (const float*)d_in[12];
    float* out = (float*)d_out;

    static int configured = 0;
    if (!configured) {
        cudaFuncSetAttribute(gemm1_mma, cudaFuncAttributeMaxDynamicSharedMemorySize, SMEM1);
        cudaFuncSetAttribute(gemm2_mma, cudaFuncAttributeMaxDynamicSharedMemorySize, SMEM2);
        configured = 1;
    }

    transpose_w<<<(F_ * H_ + F_ * F_ + 255) / 256, 256>>>(fw1, fw2);

    dim3 g1(F_ / 128, M1_ / 128);            // (3, 4608) — n-tile on fast axis
    gemm1_mma<<<g1, 256, SMEM1>>>(h_E, fb1);

    dim3 g2(F_ / 128, B_ * L_);              // (3, 1536) — n-tile on fast axis
    gemm2_mma<<<g2, 256, SMEM2>>>(h_V, fb2);

    head_kernel<<<B_ * L_, 128>>>(hw1, hb1, hw2, hb2, hw3, hb3, mask);
    reduce_kernel<<<B_, 128>>>(mask, out);
}

// round 8
// speedup vs baseline: 4.3454x; 1.3785x over previous
#include <cuda_runtime.h>
#include <cuda_fp16.h>
#include <math.h>
#include <stdint.h>

// ---------------------------------------------------------------------------
// Problem constants
// ---------------------------------------------------------------------------
#define B_  4
#define L_  384
#define H_  128
#define F_  384
#define M1_ (B_ * L_ * L_)      // 589824 edge rows

// ---------------------------------------------------------------------------
// Device scratch (allocation-free rule)
// ---------------------------------------------------------------------------
__device__ __half g_hEh[(size_t)M1_ * H_];      // fp16 copy of h_E
__device__ __half g_T1h[(size_t)M1_ * F_];      // fp16 gelu(h_E @ fw1 + fb1)
__device__ float  g_xconv[(size_t)B_ * L_ * F_];
__device__ float  g_predm[B_ * L_];
__device__ __half g_fw1T[F_ * H_];              // [n=384][k=128] fp16
__device__ __half g_fw2T[F_ * F_];              // [n=384][k=384] fp16

__device__ __forceinline__ float gelu_f(float x) {
    return 0.5f * x * (1.0f + erff(x * 0.70710678118654752440f));
}

__device__ __forceinline__ uint32_t smem_u32(const void* p) {
    uint32_t a;
    asm("{ .reg .u64 t; cvta.to.shared.u64 t, %1; cvt.u32.u64 %0, t; }" : "=r"(a) : "l"(p));
    return a;
}

// m16n8k16 fp16 MMA, fp32 accumulate.
__device__ __forceinline__ void mma16(float* c, const uint32_t* a, uint32_t b0, uint32_t b1) {
    asm volatile(
        "mma.sync.aligned.m16n8k16.row.col.f32.f16.f16.f32 "
        "{%0,%1,%2,%3}, {%4,%5,%6,%7}, {%8,%9}, {%0,%1,%2,%3};"
        : "+f"(c[0]), "+f"(c[1]), "+f"(c[2]), "+f"(c[3])
        : "r"(a[0]), "r"(a[1]), "r"(a[2]), "r"(a[3]), "r"(b0), "r"(b1));
}

#define CP_COMMIT() asm volatile("cp.async.commit_group;" ::: "memory")
#define CP_WAIT1()  asm volatile("cp.async.wait_group 1;" ::: "memory")
#define CP_WAIT0()  asm volatile("cp.async.wait_group 0;" ::: "memory")

// Async-stage a [128 rows x 32 half] block (gmem row stride ldg halves) into
// smem with row pitch 40 halves (80 B = 5x16B, keeps cp.async 16B-aligned and
// gives conflict-free fragment LDS: row stride 20 b32-words, gid*20 mod 32
// distinct). 256 threads x 2 x 16B.
__device__ __forceinline__ void stage_async_h(const __half* __restrict__ g, int ldg,
                                              uint32_t s_addr, int tid) {
#pragma unroll
    for (int i = 0; i < 2; ++i) {
        int idx = tid + i * 256;            // 0..511
        int row = idx >> 2, q = idx & 3;    // 4 x 16B per 64B row
        uint32_t dst = s_addr + (uint32_t)(row * 80 + q * 16);
        const __half* src = g + (size_t)row * ldg + q * 8;
        asm volatile("cp.async.cg.shared.global [%0], [%1], 16;" :: "r"(dst), "l"(src));
    }
}

// ---------------------------------------------------------------------------
// Dynamic smem layout (bytes)
// ---------------------------------------------------------------------------
#define SB_   10240                 // one 128x40-half buffer
#define O_A   0                     // 2 buffers
#define O_B   (2 * SB_)             // 2 buffers
#define O_BIAS (4 * SB_)            // 512 B
#define O_RED  (O_BIAS + 512)       // 2048 B (gemm2)
#define O_XACC (O_RED + 2048)       // 512 B  (gemm2)
#define SMEM1  (O_BIAS + 512)
#define SMEM2  (O_XACC + 512)

// ---------------------------------------------------------------------------
// Kernel 0a: convert h_E (fp32) -> fp16
// ---------------------------------------------------------------------------
__global__ void __launch_bounds__(256) conv_hE(const float* __restrict__ hE) {
    size_t i = ((size_t)blockIdx.x * 256 + threadIdx.x) * 4;
    float4 v = *reinterpret_cast<const float4*>(hE + i);
    __half2 h0 = __floats2half2_rn(v.x, v.y);
    __half2 h1 = __floats2half2_rn(v.z, v.w);
    *reinterpret_cast<__half2*>(g_hEh + i)     = h0;
    *reinterpret_cast<__half2*>(g_hEh + i + 2) = h1;
}

// ---------------------------------------------------------------------------
// Kernel 0b: transpose weights to [n][k] fp16
// ---------------------------------------------------------------------------
__global__ void __launch_bounds__(256) transpose_w(const float* __restrict__ fw1,
                                                   const float* __restrict__ fw2) {
    int idx = blockIdx.x * 256 + threadIdx.x;
    if (idx < F_ * H_) {
        int n = idx / H_, k = idx % H_;
        g_fw1T[idx] = __float2half_rn(fw1[k * F_ + n]);
    }
    int i2 = idx - F_ * H_;
    if (i2 >= 0 && i2 < F_ * F_) {
        int n = i2 / F_, k = i2 % F_;
        g_fw2T[i2] = __float2half_rn(fw2[k * F_ + n]);
    }
}

// ---------------------------------------------------------------------------
// Warp-level MMA over one staged K=32 chunk (2 x K=16 steps).
// Smem pitch: 20 b32-words per row. Warp tile 32(m) x 64(n).
// ---------------------------------------------------------------------------
__device__ __forceinline__ void mma_chunk(const uint32_t* Au, const uint32_t* Bu,
                                          float acc[2][8][4], int wm, int wn,
                                          int gid, int tig) {
#pragma unroll
    for (int ks = 0; ks < 2; ++ks) {
        const int kk = ks * 8;              // b32 offset along k (16 halves)
        uint32_t bf[8][2];
#pragma unroll
        for (int nt = 0; nt < 8; ++nt) {
            int n = wn * 64 + nt * 8 + gid;
            bf[nt][0] = Bu[n * 20 + kk + tig];
            bf[nt][1] = Bu[n * 20 + kk + 4 + tig];
        }
#pragma unroll
        for (int mt = 0; mt < 2; ++mt) {
            uint32_t af[4];
            int r = wm * 32 + mt * 16 + gid;
            af[0] = Au[r * 20 + kk + tig];
            af[1] = Au[(r + 8) * 20 + kk + tig];
            af[2] = Au[r * 20 + kk + 4 + tig];
            af[3] = Au[(r + 8) * 20 + kk + 4 + tig];
#pragma unroll
            for (int nt = 0; nt < 8; ++nt) mma16(acc[mt][nt], af, bf[nt][0], bf[nt][1]);
        }
    }
}

// ---------------------------------------------------------------------------
// Kernel 1: T1 = fp16(gelu(h_E @ fw1 + fb1))
//   grid (3, 4608): x = n-tile fast axis. CTA tile 128x128, warp tile 32x64.
//   K=128 in 4 chunks of 32, cp.async double-buffered, all-fp16 operands.
// ---------------------------------------------------------------------------
__global__ void __launch_bounds__(256, 2) gemm1_mma(const float* __restrict__ fb1) {
    extern __shared__ char smc[];
    const uint32_t sb = smem_u32(smc);
    float* biasS = reinterpret_cast<float*>(smc + O_BIAS);

    const int tid = threadIdx.x;
    const int wid = tid >> 5, lane = tid & 31;
    const int gid = lane >> 2, tig = lane & 3;
    const int wm = wid & 3, wn = wid >> 2;
    const int m0 = blockIdx.y * 128, n0 = blockIdx.x * 128;

    if (tid < 128) biasS[tid] = fb1[n0 + tid];

    float acc[2][8][4];
#pragma unroll
    for (int mt = 0; mt < 2; ++mt)
#pragma unroll
        for (int nt = 0; nt < 8; ++nt)
#pragma unroll
            for (int j = 0; j < 4; ++j) acc[mt][nt][j] = 0.f;

    const __half* Abase = g_hEh + (size_t)m0 * H_;
    const __half* Bbase = g_fw1T + (size_t)n0 * H_;

    stage_async_h(Abase, H_, sb + O_A, tid);
    stage_async_h(Bbase, H_, sb + O_B, tid);
    CP_COMMIT();

    for (int kc = 0; kc < 4; ++kc) {
        const int cur = kc & 1;
        if (kc + 1 < 4) {
            stage_async_h(Abase + (kc + 1) * 32, H_, sb + O_A + (1 - cur) * SB_, tid);
            stage_async_h(Bbase + (kc + 1) * 32, H_, sb + O_B + (1 - cur) * SB_, tid);
            CP_COMMIT();
            CP_WAIT1();
        } else {
            CP_WAIT0();
        }
        __syncthreads();

        const uint32_t* Au = reinterpret_cast<const uint32_t*>(smc + O_A + cur * SB_);
        const uint32_t* Bu = reinterpret_cast<const uint32_t*>(smc + O_B + cur * SB_);
        mma_chunk(Au, Bu, acc, wm, wn, gid, tig);
        __syncthreads();
    }

    // Epilogue: bias + exact-erf gelu (fp32), store fp16 half2
#pragma unroll
    for (int mt = 0; mt < 2; ++mt)
#pragma unroll
        for (int nt = 0; nt < 8; ++nt) {
            float* c = acc[mt][nt];
            int lr = wm * 32 + mt * 16 + gid;
            int lc = wn * 64 + nt * 8 + 2 * tig;
            float b0v = biasS[lc], b1v = biasS[lc + 1];
            size_t base = (size_t)(m0 + lr) * F_ + n0 + lc;
            *reinterpret_cast<__half2*>(g_T1h + base) =
                __floats2half2_rn(gelu_f(c[0] + b0v), gelu_f(c[1] + b1v));
            *reinterpret_cast<__half2*>(g_T1h + base + (size_t)8 * F_) =
                __floats2half2_rn(gelu_f(c[2] + b0v), gelu_f(c[3] + b1v));
        }
}

// ---------------------------------------------------------------------------
// Kernel 2: per (bl, n-tile): T2 = gelu(T1_bl @ fw2 + fb2);
//           xconv[bl, n] = sum_k hV[b,k,n] * T2[k,n]   (T2 never hits memory)
//   grid (3, 1536). 3 m-tiles of 128 k-edges, K=384 in 12 chunks, fp16.
// ---------------------------------------------------------------------------
__global__ void __launch_bounds__(256, 2) gemm2_mma(const float* __restrict__ hV,
                                                    const float* __restrict__ fb2) {
    extern __shared__ char smc[];
    const uint32_t sb = smem_u32(smc);
    float* biasS = reinterpret_cast<float*>(smc + O_BIAS);
    float (*red)[128] = reinterpret_cast<float (*)[128]>(smc + O_RED);
    float* xacc = reinterpret_cast<float*>(smc + O_XACC);

    const int tid = threadIdx.x;
    const int wid = tid >> 5, lane = tid & 31;
    const int gid = lane >> 2, tig = lane & 3;
    const int wm = wid & 3, wn = wid >> 2;
    const int bl = blockIdx.y, b = bl / L_;
    const int n0 = blockIdx.x * 128;

    if (tid < 128) { biasS[tid] = fb2[n0 + tid]; xacc[tid] = 0.f; }

    const __half* Bbase = g_fw2T + (size_t)n0 * F_;

    for (int mt = 0; mt < 3; ++mt) {
        float acc[2][8][4];
#pragma unroll
        for (int m2 = 0; m2 < 2; ++m2)
#pragma unroll
            for (int nt = 0; nt < 8; ++nt)
#pragma unroll
                for (int j = 0; j < 4; ++j) acc[m2][nt][j] = 0.f;

        const __half* Abase = g_T1h + (size_t)(bl * L_ + mt * 128) * F_;

        stage_async_h(Abase, F_, sb + O_A, tid);
        stage_async_h(Bbase, F_, sb + O_B, tid);
        CP_COMMIT();

        for (int kc = 0; kc < 12; ++kc) {
            const int cur = kc & 1;
            if (kc + 1 < 12) {
                stage_async_h(Abase + (kc + 1) * 32, F_, sb + O_A + (1 - cur) * SB_, tid);
                stage_async_h(Bbase + (kc + 1) * 32, F_, sb + O_B + (1 - cur) * SB_, tid);
                CP_COMMIT();
                CP_WAIT1();
            } else {
                CP_WAIT0();
            }
            __syncthreads();

            const uint32_t* Au = reinterpret_cast<const uint32_t*>(smc + O_A + cur * SB_);
            const uint32_t* Bu = reinterpret_cast<const uint32_t*>(smc + O_B + cur * SB_);
            mma_chunk(Au, Bu, acc, wm, wn, gid, tig);
            __syncthreads();
        }

        // Fused epilogue: gelu + bias, * hV, reduce over the 128 k-edge rows
        float p0[8], p1[8];
#pragma unroll
        for (int nt = 0; nt < 8; ++nt) { p0[nt] = 0.f; p1[nt] = 0.f; }

#pragma unroll
        for (int m2 = 0; m2 < 2; ++m2)
#pragma unroll
            for (int nt = 0; nt < 8; ++nt) {
                float* c = acc[m2][nt];
                int r0 = wm * 32 + m2 * 16 + gid;
                int lc = wn * 64 + nt * 8 + 2 * tig;
                float b0v = biasS[lc], b1v = biasS[lc + 1];
                const float* hv0 = hV + ((size_t)b * L_ + mt * 128 + r0) * F_ + n0 + lc;
                float2 h0 = *reinterpret_cast<const float2*>(hv0);
                float2 h1 = *reinterpret_cast<const float2*>(hv0 + (size_t)8 * F_);
                p0[nt] += gelu_f(c[0] + b0v) * h0.x + gelu_f(c[2] + b0v) * h1.x;
                p1[nt] += gelu_f(c[1] + b1v) * h0.y + gelu_f(c[3] + b1v) * h1.y;
            }

        // butterfly over gid (lanes differ in bits 2..4)
#pragma unroll
        for (int nt = 0; nt < 8; ++nt) {
#pragma unroll
            for (int off = 16; off >= 4; off >>= 1) {
                p0[nt] += __shfl_xor_sync(0xFFFFFFFFu, p0[nt], off);
                p1[nt] += __shfl_xor_sync(0xFFFFFFFFu, p1[nt], off);
            }
        }
        if (gid == 0) {
#pragma unroll
            for (int nt = 0; nt < 8; ++nt) {
                red[wm][wn * 64 + nt * 8 + 2 * tig]     = p0[nt];
                red[wm][wn * 64 + nt * 8 + 2 * tig + 1] = p1[nt];
            }
        }
        __syncthreads();
        if (tid < 128)
            xacc[tid] += red[0][tid] + red[1][tid] + red[2][tid] + red[3][tid];
        __syncthreads();
    }

    if (tid < 128) g_xconv[(size_t)bl * F_ + n0 + tid] = xacc[tid];
}

// ---------------------------------------------------------------------------
// Kernel 3: head MLP per (b,l): 384->128 gelu ->64 gelu ->1 ; pred * mask
// ---------------------------------------------------------------------------
__global__ void __launch_bounds__(128) head_kernel(
    const float* __restrict__ hw1, const float* __restrict__ hb1,
    const float* __restrict__ hw2, const float* __restrict__ hb2,
    const float* __restrict__ hw3, const float* __restrict__ hb3,
    const float* __restrict__ mask) {
    const int bl = blockIdx.x;
    const int tid = threadIdx.x;
    __shared__ float xs[F_];
    __shared__ float h1[H_];
    __shared__ float h2[H_ / 2];

    for (int i = tid; i < F_; i += 128) xs[i] = g_xconv[(size_t)bl * F_ + i];
    __syncthreads();

    float s = hb1[tid];
    for (int f = 0; f < F_; ++f) s += xs[f] * hw1[f * H_ + tid];
    h1[tid] = gelu_f(s);
    __syncthreads();

    if (tid < 64) {
        float s2 = hb2[tid];
#pragma unroll 4
        for (int h = 0; h < H_; ++h) s2 += h1[h] * hw2[h * 64 + tid];
        h2[tid] = gelu_f(s2);
    }
    __syncthreads();

    if (tid == 0) {
        float p = hb3[0];
        for (int j = 0; j < 64; ++j) p += h2[j] * hw3[j];
        g_predm[bl] = p * mask[bl];
    }
}

// ---------------------------------------------------------------------------
// Kernel 4: per-batch masked reduction
// ---------------------------------------------------------------------------
__global__ void __launch_bounds__(128) reduce_kernel(const float* __restrict__ mask,
                                                     float* __restrict__ out) {
    const int b = blockIdx.x;
    const int tid = threadIdx.x;
    __shared__ float sp[128];
    __shared__ float smk[128];

    float p = 0.f, mk = 0.f;
    for (int l = tid; l < L_; l += 128) {
        p += g_predm[b * L_ + l];
        mk += mask[b * L_ + l];
    }
    sp[tid] = p; smk[tid] = mk;
    __syncthreads();
    for (int s = 64; s > 0; s >>= 1) {
        if (tid < s) { sp[tid] += sp[tid + s]; smk[tid] += smk[tid + s]; }
        __syncthreads();
    }
    if (tid == 0) {
        float vl = smk[0] < 1.f ? 1.f : smk[0];
        out[b] = sp[0] / sqrtf(vl);
    }
}

// ---------------------------------------------------------------------------
// Launch
// ---------------------------------------------------------------------------
extern "C" void kernel_launch(void* const* d_in, const int* in_sizes, int n_in,
                              void* d_out, int out_size) {
    const float* h_V  = (const float*)d_in[0];
    const float* h_E  = (const float*)d_in[1];
    const float* mask = (const float*)d_in[2];
    const float* fw1  = (const float*)d_in[3];
    const float* fb1  = (const float*)d_in[4];
    const float* fw2  = (const float*)d_in[5];
    const float* fb2  = (const float*)d_in[6];
    const float* hw1  = (const float*)d_in[7];
    const float* hb1  = (const float*)d_in[8];
    const float* hw2  = (const float*)d_in[9];
    const float* hb2  = (const float*)d_in[10];
    const float* hw3  = (const float*)d_in[11];
    const float* hb3  = (const float*)d_in[12];
    float* out = (float*)d_out;

    static int configured = 0;
    if (!configured) {
        cudaFuncSetAttribute(gemm1_mma, cudaFuncAttributeMaxDynamicSharedMemorySize, SMEM1);
        cudaFuncSetAttribute(gemm2_mma, cudaFuncAttributeMaxDynamicSharedMemorySize, SMEM2);
        configured = 1;
    }

    conv_hE<<<((size_t)M1_ * H_) / (256 * 4), 256>>>(h_E);
    transpose_w<<<(F_ * H_ + F_ * F_ + 255) / 256, 256>>>(fw1, fw2);

    dim3 g1(F_ / 128, M1_ / 128);            // (3, 4608)
    gemm1_mma<<<g1, 256, SMEM1>>>(fb1);

    dim3 g2(F_ / 128, B_ * L_);              // (3, 1536)
    gemm2_mma<<<g2, 256, SMEM2>>>(h_V, fb2);

    head_kernel<<<B_ * L_, 128>>>(hw1, hb1, hw2, hb2, hw3, hb3, mask);
    reduce_kernel<<<B_, 128>>>(mask, out);
}